// round 1
// baseline (speedup 1.0000x reference)
#include <cuda_runtime.h>
#include <math.h>

#define BB 16
#define TT 1024
#define DD 256
#define KK 64
#define JJ 1024            // prefix tables indexed 0..JJ inclusive

#define PI_F 3.14159265358979323846f

// ---- persistent device scratch (static allocation only, per harness rules) ----
__device__ double g_acc;
__device__ double g_crp;
__device__ float  g_stc[(JJ + 1) * DD];  // prefix over j of [T1(d,j) + log(c1(d,j))], layout [j][d]
__device__ float  g_sc0[(JJ + 1) * DD];  // prefix over j of log(c0_0(d) + j)
__device__ float  g_scs[(JJ + 1) * DD];  // prefix over j of log(c1_0(d) + c0_0(d) + j)
__device__ int    g_perm[BB * TT];
__device__ int    g_off[BB * KK];
__device__ int    g_cnt[BB * KK];

// ---- kernel 1: raw per-(d,j) table entries + zero accumulators ----
__global__ void k_tables(const float* __restrict__ lcg, const float* __restrict__ spl) {
    int id = blockIdx.x * blockDim.x + threadIdx.x;   // JJ*DD threads
    if (id == 0) { g_acc = 0.0; g_crp = 0.0; }
    int d = id % DD;
    int j = id / DD;                                  // j in [0, JJ)
    float c   = expf(lcg[d]);
    float tc4 = 2.0f * c + 4.0f;                      // kap0 + 1  (= c1_0)
    float c00 = tc4 * expf(spl[d]);                   // c0_0
    float jf  = (float)j;
    float a    = c + 0.5f * jf;                       // a_k at n1=j
    float kap  = tc4 - 1.0f + jf;                     // kap_k
    float kap1 = tc4 + jf;                            // kap_k + 1
    float nu   = 2.0f * c + jf;                       // 2*a_k
    float g    = kap1 / (a * kap);                    // sig2 = b * g
    float t1 = lgammaf(a + 0.5f) - lgammaf(a)
             - 0.5f * logf(PI_F * nu) - 0.5f * logf(g);
    g_stc[j * DD + d] = t1 + logf(tc4 + jf);          // + log(c1k)
    g_sc0[j * DD + d] = logf(c00 + jf);               // log(c0k) at n0=j
    g_scs[j * DD + d] = logf(tc4 + c00 + jf);         // log(c1k+c0k) at ck=j
}

// ---- kernel 2: in-place exclusive prefix over j for each (table, d) ----
__global__ void k_prefix() {
    int d = threadIdx.x;                              // 3 blocks x DD threads
    float* A = (blockIdx.x == 0) ? g_stc : (blockIdx.x == 1) ? g_sc0 : g_scs;
    float s = 0.0f;
    for (int j = 0; j < JJ; ++j) {
        float v = A[j * DD + d];
        A[j * DD + d] = s;
        s += v;
    }
    A[JJ * DD + d] = s;
}

// ---- kernel 3: bucket steps by cluster (stable), counts/offsets, CRP sum ----
__global__ void k_bucket(const int* __restrict__ z) {
    __shared__ int   zrow[TT];
    __shared__ int   cnt_ks[KK * 4];
    __shared__ int   off_k[KK];
    __shared__ float red[KK];
    int b = blockIdx.x, tid = threadIdx.x;            // BB blocks x 256 threads
    for (int i = tid; i < TT; i += 256) zrow[i] = z[b * TT + i];
    __syncthreads();
    int k = tid >> 2, s = tid & 3;
    int t0 = s * (TT / 4), t1 = t0 + TT / 4;
    int c = 0;
    for (int t = t0; t < t1; ++t) c += (zrow[t] == k);
    cnt_ks[tid] = c;
    __syncthreads();
    if (tid == 0) {
        int o = 0;
        for (int kk = 0; kk < KK; ++kk) {
            off_k[kk] = o;
            o += cnt_ks[kk * 4 + 0] + cnt_ks[kk * 4 + 1]
               + cnt_ks[kk * 4 + 2] + cnt_ks[kk * 4 + 3];
        }
    }
    __syncthreads();
    int myoff = off_k[k];
    for (int ss = 0; ss < s; ++ss) myoff += cnt_ks[k * 4 + ss];
    int cur = myoff;
    for (int t = t0; t < t1; ++t)
        if (zrow[t] == k) g_perm[b * TT + cur++] = t;
    if (s == 0) {
        int ck = cnt_ks[k * 4 + 0] + cnt_ks[k * 4 + 1]
               + cnt_ks[k * 4 + 2] + cnt_ks[k * 4 + 3];
        g_cnt[b * KK + k] = ck;
        g_off[b * KK + k] = off_k[k];
        // sum over occurrences i of log(max(i,1)) == lgamma(cnt)  (ALPHA = 1)
        red[k] = (ck > 0) ? lgammaf((float)ck) : 0.0f;
    }
    __syncthreads();
    if (tid == 0) {
        float sum = 0.0f;
        for (int kk = 0; kk < KK; ++kk) sum += red[kk];
        sum -= lgammaf((float)(TT + 1));              // sum_t log(t + ALPHA)
        atomicAdd(&g_crp, (double)sum);
    }
}

// ---- kernel 4: main — one chain (b,k,d) per thread, pipelined X loads ----
__global__ void __launch_bounds__(DD) k_main(const float* __restrict__ X,
                                             const float* __restrict__ loc,
                                             const float* __restrict__ lcg,
                                             const float* __restrict__ lsc) {
    int b = blockIdx.x / KK, k = blockIdx.x % KK;
    int d = threadIdx.x;
    int cnt = g_cnt[b * KK + k];
    int off = g_off[b * KK + k];
    __shared__ int tbuf[TT];
    for (int i = d; i < cnt; i += DD) tbuf[i] = g_perm[b * TT + off + i];
    __syncthreads();

    float c    = expf(lcg[d]);
    float m    = loc[d];
    float bb   = expf(lsc[d]);
    float kap1 = 2.0f * c + 4.0f;                     // kap_k + 1, n1 = 0
    float coef = c + 0.5f;                            // (nu+1)/2 = a + 0.5
    float acc  = 0.0f;
    int   n1   = 0;

    const float* Xbd = X + (size_t)b * TT * DD + d;
    const int PF = 8;
    float xp[PF];
#pragma unroll
    for (int p = 0; p < PF; ++p)
        xp[p] = (p < cnt) ? __ldg(Xbd + (size_t)tbuf[p] * DD) : 0.0f;

    for (int base = 0; base < cnt; base += PF) {
#pragma unroll
        for (int p = 0; p < PF; ++p) {
            int i = base + p;
            if (i < cnt) {
                float x = xp[p];
                int ip = i + PF;
                if (ip < cnt) xp[p] = __ldg(Xbd + (size_t)tbuf[ip] * DD);
                if (x > 0.0f) {
                    float tl   = __logf(x);
                    float diff = tl - m;
                    float rk1  = __fdividef(1.0f, kap1);
                    float sres = 0.5f * diff * diff * (1.0f - rk1);
                    float q    = __fdividef(sres, bb);
                    acc -= tl + 0.5f * __logf(bb) + coef * __logf(1.0f + q);
                    m  = fmaf(diff, rk1, m);
                    bb += sres;
                    kap1 += 1.0f;
                    coef += 0.5f;
                    n1++;
                }
            }
        }
    }

    int n0 = cnt - n1;
    acc += g_stc[n1 * DD + d] + g_sc0[n0 * DD + d] - g_scs[cnt * DD + d];

    __shared__ float rbuf[DD];
    rbuf[d] = acc;
    __syncthreads();
    for (int st = DD / 2; st > 0; st >>= 1) {
        if (d < st) rbuf[d] += rbuf[d + st];
        __syncthreads();
    }
    if (d == 0) atomicAdd(&g_acc, (double)rbuf[0]);
}

// ---- kernel 5: finalize scalar ----
__global__ void k_final(float* out) {
    out[0] = (float)(-(g_acc + g_crp) / (double)BB);
}

extern "C" void kernel_launch(void* const* d_in, const int* in_sizes, int n_in,
                              void* d_out, int out_size) {
    const float* X   = (const float*)d_in[0];
    const int*   z   = (const int*)d_in[1];
    const float* loc = (const float*)d_in[2];
    const float* lcg = (const float*)d_in[3];
    const float* lsc = (const float*)d_in[4];
    const float* spl = (const float*)d_in[5];

    k_tables<<<(JJ * DD) / 256, 256>>>(lcg, spl);
    k_prefix<<<3, DD>>>();
    k_bucket<<<BB, 256>>>(z);
    k_main<<<BB * KK, DD>>>(X, loc, lcg, lsc);
    k_final<<<1, 1>>>((float*)d_out);
}

// round 3
// speedup vs baseline: 2.1042x; 2.1042x over previous
#include <cuda_runtime.h>
#include <math.h>

#define BB 16
#define TT 1024
#define DD 256
#define KK 64
#define NBLK (BB * KK)
#define LOG2PI 1.8378770664093453f

// ---- persistent device scratch ----
__device__ double g_acc;
__device__ float  g_crp_part[BB];
__device__ float  g_constd[DD];
__device__ int    g_perm[BB * TT];   // stores t*DD (element offset)
__device__ int    g_off[BB * KK];
__device__ int    g_cnt[BB * KK];
__device__ int    g_done;

// ---- kernel 1: bucket steps by cluster + CRP partials + per-d lgamma constants ----
__global__ void k_prep(const int* __restrict__ z,
                       const float* __restrict__ lcg,
                       const float* __restrict__ spl) {
    __shared__ int   zrow[TT];
    __shared__ int   cnt_ks[KK * 4];
    __shared__ int   off_k[KK];
    __shared__ float red[KK];
    int b = blockIdx.x, tid = threadIdx.x;            // BB blocks x 256 threads
    if (b == 0 && tid == 0) { g_acc = 0.0; g_done = 0; }
    for (int i = tid; i < TT; i += 256) zrow[i] = z[b * TT + i];
    __syncthreads();
    int k = tid >> 2, s = tid & 3;
    int t0 = s * (TT / 4), t1 = t0 + TT / 4;
    int c = 0;
    for (int t = t0; t < t1; ++t) c += (zrow[t] == k);
    cnt_ks[tid] = c;
    __syncthreads();
    if (tid == 0) {
        int o = 0;
        for (int kk = 0; kk < KK; ++kk) {
            off_k[kk] = o;
            o += cnt_ks[kk * 4 + 0] + cnt_ks[kk * 4 + 1]
               + cnt_ks[kk * 4 + 2] + cnt_ks[kk * 4 + 3];
        }
    }
    __syncthreads();
    int myoff = off_k[k];
    for (int ss = 0; ss < s; ++ss) myoff += cnt_ks[k * 4 + ss];
    int cur = myoff;
    for (int t = t0; t < t1; ++t)
        if (zrow[t] == k) g_perm[b * TT + cur++] = t * DD;
    if (s == 0) {
        int ck = cnt_ks[k * 4 + 0] + cnt_ks[k * 4 + 1]
               + cnt_ks[k * 4 + 2] + cnt_ks[k * 4 + 3];
        g_cnt[b * KK + k] = ck;
        g_off[b * KK + k] = off_k[k];
        // CRP numerator: sum_i log(max(i,1)) over occurrences == lgamma(cnt)  (ALPHA=1)
        red[k] = (ck > 0) ? lgammaf((float)ck) : 0.0f;
    }
    __syncthreads();
    if (tid == 0) {
        float sum = 0.0f;
        for (int kk = 0; kk < KK; ++kk) sum += red[kk];
        // CRP denominator: sum_t log(t + ALPHA) = lgamma(T+1), PER batch element
        g_crp_part[b] = sum - lgammaf((float)(TT + 1));
    }
    // per-d lgamma constants (block 0 only; 256 threads = 256 dims)
    if (b == 0) {
        int d = tid;
        float cc  = expf(lcg[d]);
        float tc4 = 2.0f * cc + 4.0f;                 // kap0 + 1 = c1_0
        float c00 = tc4 * expf(spl[d]);               // c0_0
        float s0  = tc4 + c00;
        g_constd[d] = -lgammaf(cc) - 0.5f * lgammaf(tc4) - 0.5f * lgammaf(tc4 - 1.0f)
                      - lgammaf(c00) + lgammaf(s0);
    }
}

// ---- kernel 2: main — one chain (b,k,d) per thread, closed-form epilogue,
//      last block finalizes the scalar output ----
__global__ void __launch_bounds__(DD) k_main(const float* __restrict__ X,
                                             const float* __restrict__ loc,
                                             const float* __restrict__ lcg,
                                             const float* __restrict__ lsc,
                                             const float* __restrict__ spl,
                                             float* __restrict__ out) {
    int bk = blockIdx.x;
    int b  = bk / KK;
    int cnt = g_cnt[bk];
    int off = g_off[bk];
    __shared__ int tbuf[TT];
    for (int i = threadIdx.x; i < cnt; i += DD) tbuf[i] = g_perm[b * TT + off + i];
    __syncthreads();

    int d = threadIdx.x;
    float cc   = expf(lcg[d]);
    float m    = loc[d];
    float lb0  = lsc[d];
    float bb   = expf(lb0);
    float tc4  = 2.0f * cc + 4.0f;
    float kap1 = tc4;                                 // kap_k + 1 at n1 = 0
    float acc  = 0.0f;
    int   n1   = 0;

    const float* Xb = X + (size_t)b * TT * DD + d;
    const int PF = 8;
    float xp[PF];
#pragma unroll
    for (int p = 0; p < PF; ++p)
        xp[p] = (p < cnt) ? __ldg(Xb + tbuf[p]) : 0.0f;

    for (int base = 0; base < cnt; base += PF) {
#pragma unroll
        for (int p = 0; p < PF; ++p) {
            int i = base + p;
            if (i < cnt) {
                float x = xp[p];
                int ip = i + PF;
                if (ip < cnt) xp[p] = __ldg(Xb + tbuf[ip]);
                if (x > 0.0f) {
                    float tl   = __logf(x);
                    float diff = tl - m;
                    float rk   = __fdividef(1.0f, kap1);
                    float s    = 0.5f * diff * diff * (1.0f - rk);
                    acc -= tl;
                    m    = fmaf(diff, rk, m);
                    bb  += s;
                    kap1 += 1.0f;
                    n1++;
                }
            }
        }
    }

    int   n0  = cnt - n1;
    float fn1 = (float)n1;
    // dynamic part: Sum_i [ -1/2 log b_i - (a_i+1/2) log1p(q_i) ]
    //             = -[ cc*(log b_n - lb0) + (n1/2)*log b_n ]   (Abel telescoping)
    acc -= 0.5f * fn1 * lb0 + (cc + 0.5f * fn1) * (logf(bb) - lb0);
    // static telescoped lgamma terms (Student-t + Beta-Bernoulli combined) + constants
    acc += g_constd[d]
         + lgammaf(fmaf(0.5f, fn1, cc))
         + 0.5f * lgammaf(tc4 + fn1)
         + 0.5f * lgammaf(tc4 - 1.0f + fn1)
         - 0.5f * fn1 * LOG2PI;
    float c00 = tc4 * expf(spl[d]);
    acc += lgammaf(c00 + (float)n0) - lgammaf(tc4 + c00 + (float)cnt);

    // reduce within block
#pragma unroll
    for (int o = 16; o; o >>= 1) acc += __shfl_xor_sync(0xffffffffu, acc, o);
    __shared__ float wsum[DD / 32];
    int lane = d & 31, wid = d >> 5;
    if (lane == 0) wsum[wid] = acc;
    __syncthreads();
    if (d == 0) {
        float s = 0.0f;
#pragma unroll
        for (int w = 0; w < DD / 32; ++w) s += wsum[w];
        atomicAdd(&g_acc, (double)s);
        __threadfence();
        int prev = atomicAdd(&g_done, 1);
        if (prev == NBLK - 1) {
            double tot = atomicAdd(&g_acc, 0.0);      // read-after-fence
            float cr = 0.0f;
#pragma unroll
            for (int i = 0; i < BB; ++i) cr += g_crp_part[i];
            out[0] = (float)(-(tot + (double)cr) / (double)BB);
        }
    }
}

extern "C" void kernel_launch(void* const* d_in, const int* in_sizes, int n_in,
                              void* d_out, int out_size) {
    const float* X   = (const float*)d_in[0];
    const int*   z   = (const int*)d_in[1];
    const float* loc = (const float*)d_in[2];
    const float* lcg = (const float*)d_in[3];
    const float* lsc = (const float*)d_in[4];
    const float* spl = (const float*)d_in[5];

    k_prep<<<BB, 256>>>(z, lcg, spl);
    k_main<<<NBLK, DD>>>(X, loc, lcg, lsc, spl, (float*)d_out);
}

// round 4
// speedup vs baseline: 2.3353x; 1.1098x over previous
#include <cuda_runtime.h>
#include <math.h>

#define BB 16
#define TT 1024
#define DD 256
#define KK 64
#define NBLK (BB * KK)
#define LOG2PI 1.8378770664093453f

// ---- persistent device scratch ----
__device__ double g_acc;
__device__ float  g_crp_part[BB];
__device__ float  g_constd[DD];
__device__ int    g_perm[BB * TT];   // stores t*(DD/2)  (float2 element offset)
__device__ int    g_off[BB * KK];
__device__ int    g_cnt[BB * KK];
__device__ int    g_done;

// fast lgamma: shift-by-8 + Stirling with two correction terms.
// valid for x > 0 up to ~1e4; abs err ~1e-7 for x >= ~0.7
__device__ __forceinline__ float lgf(float x) {
    float p = x * (x + 1.0f) * (x + 2.0f) * (x + 3.0f)
                * (x + 4.0f) * (x + 5.0f) * (x + 6.0f) * (x + 7.0f);
    float z  = x + 8.0f;
    float r  = __fdividef(1.0f, z);
    float lz = __logf(z);
    float lg = fmaf(z - 0.5f, lz, -z) + 0.91893853320467274f
             + r * fmaf(-0.0027777778f, r * r, 0.083333333f);
    return lg - __logf(p);
}

// ---- kernel 1: bucket steps by cluster + CRP partials + per-d lgamma constants ----
__global__ void k_prep(const int* __restrict__ z,
                       const float* __restrict__ lcg,
                       const float* __restrict__ spl) {
    __shared__ int   zrow[TT];
    __shared__ int   cnt_ks[KK * 4];
    __shared__ int   off_k[KK];
    __shared__ float red[KK];
    int b = blockIdx.x, tid = threadIdx.x;            // BB blocks x 256 threads
    if (b == 0 && tid == 0) { g_acc = 0.0; g_done = 0; }
    for (int i = tid; i < TT; i += 256) zrow[i] = z[b * TT + i];
    __syncthreads();
    int k = tid >> 2, s = tid & 3;
    int t0 = s * (TT / 4), t1 = t0 + TT / 4;
    int c = 0;
    for (int t = t0; t < t1; ++t) c += (zrow[t] == k);
    cnt_ks[tid] = c;
    __syncthreads();
    if (tid == 0) {
        int o = 0;
        for (int kk = 0; kk < KK; ++kk) {
            off_k[kk] = o;
            o += cnt_ks[kk * 4 + 0] + cnt_ks[kk * 4 + 1]
               + cnt_ks[kk * 4 + 2] + cnt_ks[kk * 4 + 3];
        }
    }
    __syncthreads();
    int myoff = off_k[k];
    for (int ss = 0; ss < s; ++ss) myoff += cnt_ks[k * 4 + ss];
    int cur = myoff;
    for (int t = t0; t < t1; ++t)
        if (zrow[t] == k) g_perm[b * TT + cur++] = t * (DD / 2);
    if (s == 0) {
        int ck = cnt_ks[k * 4 + 0] + cnt_ks[k * 4 + 1]
               + cnt_ks[k * 4 + 2] + cnt_ks[k * 4 + 3];
        g_cnt[b * KK + k] = ck;
        g_off[b * KK + k] = off_k[k];
        // CRP numerator: sum_i log(max(i,1)) over occurrences == lgamma(cnt)  (ALPHA=1)
        red[k] = (ck > 0) ? lgf((float)ck) : 0.0f;
    }
    __syncthreads();
    if (tid == 0) {
        float sum = 0.0f;
        for (int kk = 0; kk < KK; ++kk) sum += red[kk];
        // CRP denominator: sum_t log(t + ALPHA) = lgamma(T+1), per batch element
        g_crp_part[b] = sum - lgf((float)(TT + 1));
    }
    // per-d lgamma constants (block 0 only; 256 threads = 256 dims)
    if (b == 0) {
        int d = tid;
        float cc  = __expf(lcg[d]);
        float tc4 = 2.0f * cc + 4.0f;                 // kap0 + 1 = c1_0
        float c00 = tc4 * __expf(spl[d]);             // c0_0
        g_constd[d] = -lgf(cc) - 0.5f * lgf(tc4) - 0.5f * lgf(tc4 - 1.0f)
                      - lgf(c00) + lgf(tc4 + c00);
    }
}

// per-dim epilogue from sufficient statistics
__device__ __forceinline__ float epi(float n1f, float cntf, float S1, float S2,
                                     float m0, float clcg, float lb0, float cspl,
                                     float cd) {
    float cc   = __expf(clcg);
    float b0   = __expf(lb0);
    float tc4  = 2.0f * cc + 4.0f;                    // kap0 + 1
    float kap0 = tc4 - 1.0f;
    float c00  = tc4 * __expf(cspl);
    float n0f  = cntf - n1f;
    // closed-form final NIG scale b_n (order independent)
    float rn   = (n1f > 0.0f) ? __fdividef(1.0f, n1f) : 0.0f;
    float tbar = S1 * rn;
    float dm   = tbar - m0;
    float bb   = b0 + 0.5f * (S2 - S1 * tbar)
               + __fdividef(kap0 * n1f * dm * dm, 2.0f * (kap0 + n1f));
    float acc  = -S1;                                 // -sum log x  (Jacobian)
    acc -= 0.5f * n1f * lb0 + fmaf(0.5f, n1f, cc) * (__logf(bb) - lb0);
    acc += cd
         + lgf(fmaf(0.5f, n1f, cc))
         + 0.5f * lgf(tc4 + n1f)
         + 0.5f * lgf(kap0 + n1f)
         - 0.5f * n1f * LOG2PI;
    acc += lgf(c00 + n0f) - lgf(tc4 + c00 + cntf);
    return acc;
}

// ---- kernel 2: main — block (b,k); 128 threads, 2 dims/thread via float2 ----
__global__ void __launch_bounds__(128) k_main(const float* __restrict__ X,
                                              const float* __restrict__ loc,
                                              const float* __restrict__ lcg,
                                              const float* __restrict__ lsc,
                                              const float* __restrict__ spl,
                                              float* __restrict__ out) {
    int bk = blockIdx.x;
    int b  = bk / KK;
    int cnt = g_cnt[bk];
    int off = g_off[bk];
    __shared__ int tbuf[TT];
    int tid = threadIdx.x;
    for (int i = tid; i < cnt; i += 128) tbuf[i] = g_perm[b * TT + off + i];
    __syncthreads();

    const float2* Xb2 = reinterpret_cast<const float2*>(X + (size_t)b * TT * DD) + tid;

    float n1a = 0.0f, S1a = 0.0f, S2a = 0.0f;
    float n1b = 0.0f, S1b = 0.0f, S2b = 0.0f;

    const int PF = 8;
    float2 xp[PF];
#pragma unroll
    for (int p = 0; p < PF; ++p)
        if (p < cnt) xp[p] = __ldg(Xb2 + tbuf[p]);

    int full = cnt & ~(PF - 1);
    for (int base = 0; base < full; base += PF) {
#pragma unroll
        for (int p = 0; p < PF; ++p) {
            float2 x = xp[p];
            int ip = base + p + PF;
            if (ip < cnt) xp[p] = __ldg(Xb2 + tbuf[ip]);
            if (x.x > 0.0f) {
                float t = __logf(x.x);
                S1a += t; S2a = fmaf(t, t, S2a); n1a += 1.0f;
            }
            if (x.y > 0.0f) {
                float t = __logf(x.y);
                S1b += t; S2b = fmaf(t, t, S2b); n1b += 1.0f;
            }
        }
    }
    for (int i = full; i < cnt; ++i) {
        float2 x = xp[i - full];
        if (x.x > 0.0f) {
            float t = __logf(x.x);
            S1a += t; S2a = fmaf(t, t, S2a); n1a += 1.0f;
        }
        if (x.y > 0.0f) {
            float t = __logf(x.y);
            S1b += t; S2b = fmaf(t, t, S2b); n1b += 1.0f;
        }
    }

    float cntf = (float)cnt;
    float2 l2  = __ldg(reinterpret_cast<const float2*>(loc) + tid);
    float2 c2  = __ldg(reinterpret_cast<const float2*>(lcg) + tid);
    float2 s2  = __ldg(reinterpret_cast<const float2*>(lsc) + tid);
    float2 p2  = __ldg(reinterpret_cast<const float2*>(spl) + tid);
    float2 cd2 = *(reinterpret_cast<const float2*>(g_constd) + tid);

    float acc = epi(n1a, cntf, S1a, S2a, l2.x, c2.x, s2.x, p2.x, cd2.x)
              + epi(n1b, cntf, S1b, S2b, l2.y, c2.y, s2.y, p2.y, cd2.y);

    // block reduce (128 threads)
#pragma unroll
    for (int o = 16; o; o >>= 1) acc += __shfl_xor_sync(0xffffffffu, acc, o);
    __shared__ float wsum[4];
    int lane = tid & 31, wid = tid >> 5;
    if (lane == 0) wsum[wid] = acc;
    __syncthreads();
    if (tid == 0) {
        float s = wsum[0] + wsum[1] + wsum[2] + wsum[3];
        atomicAdd(&g_acc, (double)s);
        __threadfence();
        int prev = atomicAdd(&g_done, 1);
        if (prev == NBLK - 1) {
            double tot = atomicAdd(&g_acc, 0.0);      // read-after-fence
            float cr = 0.0f;
#pragma unroll
            for (int i = 0; i < BB; ++i) cr += g_crp_part[i];
            out[0] = (float)(-(tot + (double)cr) / (double)BB);
        }
    }
}

extern "C" void kernel_launch(void* const* d_in, const int* in_sizes, int n_in,
                              void* d_out, int out_size) {
    const float* X   = (const float*)d_in[0];
    const int*   z   = (const int*)d_in[1];
    const float* loc = (const float*)d_in[2];
    const float* lcg = (const float*)d_in[3];
    const float* lsc = (const float*)d_in[4];
    const float* spl = (const float*)d_in[5];

    k_prep<<<BB, 256>>>(z, lcg, spl);
    k_main<<<NBLK, 128>>>(X, loc, lcg, lsc, spl, (float*)d_out);
}

// round 6
// speedup vs baseline: 2.5497x; 1.0918x over previous
#include <cuda_runtime.h>
#include <math.h>

#define BB 16
#define TT 1024
#define DD 256
#define KK 64
#define NBLK (BB * KK)
#define LOG2PI 1.8378770664093453f

// ---- persistent device scratch ----
__device__ double g_acc;
__device__ float  g_crp_part[BB];
__device__ float  g_constd[DD];
__device__ int    g_perm[BB * TT];   // stores t*DD (element offset)
__device__ int    g_off[BB * KK];
__device__ int    g_cnt[BB * KK];
__device__ int    g_done;

// fast lgamma: shift-by-8 + Stirling with two correction terms.
// abs err ~1e-7 for x >= ~0.5
__device__ __forceinline__ float lgf(float x) {
    float p = x * (x + 1.0f) * (x + 2.0f) * (x + 3.0f)
                * (x + 4.0f) * (x + 5.0f) * (x + 6.0f) * (x + 7.0f);
    float z  = x + 8.0f;
    float r  = __fdividef(1.0f, z);
    float lz = __logf(z);
    float lg = fmaf(z - 0.5f, lz, -z) + 0.91893853320467274f
             + r * fmaf(-0.0027777778f, r * r, 0.083333333f);
    return lg - __logf(p);
}

// ---- kernel 1: bucket steps by cluster + CRP partials + per-d constants ----
__global__ void k_prep(const int* __restrict__ z,
                       const float* __restrict__ lcg,
                       const float* __restrict__ spl) {
    __shared__ int   zrow[TT];
    __shared__ int   cnt_ks[KK * 4];
    __shared__ int   off_k[KK];
    __shared__ float red[KK];
    int b = blockIdx.x, tid = threadIdx.x;            // BB blocks x 256 threads
    if (b == 0 && tid == 0) { g_acc = 0.0; g_done = 0; }
    for (int i = tid; i < TT; i += 256) zrow[i] = z[b * TT + i];
    __syncthreads();
    int k = tid >> 2, s = tid & 3;
    int t0 = s * (TT / 4), t1 = t0 + TT / 4;
    int c = 0;
    for (int t = t0; t < t1; ++t) c += (zrow[t] == k);
    cnt_ks[tid] = c;
    __syncthreads();
    if (tid == 0) {
        int o = 0;
        for (int kk = 0; kk < KK; ++kk) {
            off_k[kk] = o;
            o += cnt_ks[kk * 4 + 0] + cnt_ks[kk * 4 + 1]
               + cnt_ks[kk * 4 + 2] + cnt_ks[kk * 4 + 3];
        }
    }
    __syncthreads();
    int myoff = off_k[k];
    for (int ss = 0; ss < s; ++ss) myoff += cnt_ks[k * 4 + ss];
    int cur = myoff;
    for (int t = t0; t < t1; ++t)
        if (zrow[t] == k) g_perm[b * TT + cur++] = t * DD;
    if (s == 0) {
        int ck = cnt_ks[k * 4 + 0] + cnt_ks[k * 4 + 1]
               + cnt_ks[k * 4 + 2] + cnt_ks[k * 4 + 3];
        g_cnt[b * KK + k] = ck;
        g_off[b * KK + k] = off_k[k];
        // CRP numerator: sum_i log(max(i,1)) over occurrences == lgamma(cnt)  (ALPHA=1)
        red[k] = (ck > 0) ? lgf((float)ck) : 0.0f;
    }
    __syncthreads();
    if (tid == 0) {
        float sum = 0.0f;
        for (int kk = 0; kk < KK; ++kk) sum += red[kk];
        // CRP denominator: sum_t log(t + ALPHA) = lgamma(T+1), per batch element
        g_crp_part[b] = sum - lgf((float)(TT + 1));
    }
    // per-d lgamma constants (block 0; 256 threads = 256 dims)
    if (b == 0) {
        int d = tid;
        float cc   = __expf(lcg[d]);
        float kap0 = 2.0f * cc + 3.0f;
        float tc4  = kap0 + 1.0f;                     // c1_0
        float c00  = tc4 * __expf(spl[d]);            // c0_0
        // -lgf(cc) - 0.5 lgf(tc4) - 0.5 lgf(kap0) - lgf(c00) + lgf(tc4+c00)
        g_constd[d] = -lgf(cc) - lgf(kap0) - 0.5f * __logf(kap0)
                      - lgf(c00) + lgf(tc4 + c00);
    }
}

// ---- kernel 2: main — block (b,k); 256 threads, one dim per thread ----
__global__ void __launch_bounds__(DD) k_main(const float* __restrict__ X,
                                             const float* __restrict__ loc,
                                             const float* __restrict__ lcg,
                                             const float* __restrict__ lsc,
                                             const float* __restrict__ spl,
                                             float* __restrict__ out) {
    int bk = blockIdx.x;
    int b  = bk / KK;
    int cnt = g_cnt[bk];
    int off = g_off[bk];
    __shared__ int tbuf[TT];
    int tid = threadIdx.x;
    for (int i = tid; i < cnt; i += DD) tbuf[i] = g_perm[b * TT + off + i];
    __syncthreads();

    const float* Xb = X + (size_t)b * TT * DD + tid;

    float n1 = 0.0f, S1 = 0.0f, S2 = 0.0f;

    int i = 0;
    for (; i + 4 <= cnt; i += 4) {                    // unguarded quad: batched LDGs
        int o0 = tbuf[i], o1 = tbuf[i + 1], o2 = tbuf[i + 2], o3 = tbuf[i + 3];
        float x0 = __ldg(Xb + o0);
        float x1 = __ldg(Xb + o1);
        float x2 = __ldg(Xb + o2);
        float x3 = __ldg(Xb + o3);
        // select (NOT clamp): keep x when nonzero, else 1 -> log contributes 0
        float t0 = __logf(x0 > 0.0f ? x0 : 1.0f);
        float t1 = __logf(x1 > 0.0f ? x1 : 1.0f);
        float t2 = __logf(x2 > 0.0f ? x2 : 1.0f);
        float t3 = __logf(x3 > 0.0f ? x3 : 1.0f);
        S1 += t0 + t1 + t2 + t3;
        S2 = fmaf(t0, t0, S2); S2 = fmaf(t1, t1, S2);
        S2 = fmaf(t2, t2, S2); S2 = fmaf(t3, t3, S2);
        n1 += (x0 > 0.0f) + (x1 > 0.0f) + (x2 > 0.0f) + (x3 > 0.0f);
    }
    for (; i < cnt; ++i) {
        float x = __ldg(Xb + tbuf[i]);
        float t = __logf(x > 0.0f ? x : 1.0f);
        S1 += t; S2 = fmaf(t, t, S2); n1 += (x > 0.0f);
    }

    // ---- epilogue from sufficient statistics ----
    float cc   = __expf(lcg[tid]);
    float m0   = loc[tid];
    float lb0  = lsc[tid];
    float b0   = __expf(lb0);
    float kap0 = 2.0f * cc + 3.0f;
    float tc4  = kap0 + 1.0f;
    float c00  = tc4 * __expf(spl[tid]);
    float cntf = (float)cnt;
    float n0f  = cntf - n1;

    // closed-form final NIG scale b_n (order independent)
    float rn   = (n1 > 0.0f) ? __fdividef(1.0f, n1) : 0.0f;
    float tbar = S1 * rn;
    float dm   = tbar - m0;
    float bb   = b0 + 0.5f * (S2 - S1 * tbar)
               + __fdividef(kap0 * n1 * dm * dm, 2.0f * (kap0 + n1));

    float acc = -S1;                                  // Jacobian
    acc -= 0.5f * n1 * lb0 + fmaf(0.5f, n1, cc) * (__logf(bb) - lb0);
    // 0.5 lgf(tc4+n1) + 0.5 lgf(kap0+n1) = lgf(kap0+n1) + 0.5 log(kap0+n1)
    float kn = kap0 + n1;
    acc += g_constd[tid]
         + lgf(fmaf(0.5f, n1, cc))
         + lgf(kn) + 0.5f * __logf(kn)
         - 0.5f * n1 * LOG2PI;
    acc += lgf(c00 + n0f) - lgf(tc4 + c00 + cntf);

    // block reduce (256 threads)
#pragma unroll
    for (int o = 16; o; o >>= 1) acc += __shfl_xor_sync(0xffffffffu, acc, o);
    __shared__ float wsum[DD / 32];
    int lane = tid & 31, wid = tid >> 5;
    if (lane == 0) wsum[wid] = acc;
    __syncthreads();
    if (tid == 0) {
        float s = 0.0f;
#pragma unroll
        for (int w = 0; w < DD / 32; ++w) s += wsum[w];
        atomicAdd(&g_acc, (double)s);
        __threadfence();
        int prev = atomicAdd(&g_done, 1);
        if (prev == NBLK - 1) {
            double tot = atomicAdd(&g_acc, 0.0);      // read-after-fence
            float cr = 0.0f;
#pragma unroll
            for (int i2 = 0; i2 < BB; ++i2) cr += g_crp_part[i2];
            out[0] = (float)(-(tot + (double)cr) / (double)BB);
        }
    }
}

extern "C" void kernel_launch(void* const* d_in, const int* in_sizes, int n_in,
                              void* d_out, int out_size) {
    const float* X   = (const float*)d_in[0];
    const int*   z   = (const int*)d_in[1];
    const float* loc = (const float*)d_in[2];
    const float* lcg = (const float*)d_in[3];
    const float* lsc = (const float*)d_in[4];
    const float* spl = (const float*)d_in[5];

    k_prep<<<BB, 256>>>(z, lcg, spl);
    k_main<<<NBLK, DD>>>(X, loc, lcg, lsc, spl, (float*)d_out);
}

// round 7
// speedup vs baseline: 4.9975x; 1.9600x over previous
#include <cuda_runtime.h>
#include <math.h>

#define BB 16
#define TT 1024
#define DD 256
#define KK 64
#define NBLK (BB * KK)
#define LOG2PI 1.8378770664093453f

// ---- persistent device scratch (zero-initialized at module load; the
//      finalizer restores zeros so every launch sees the same state) ----
__device__ double g_acc;
__device__ int    g_done;

// fast lgamma: shift-by-8 + Stirling with two correction terms.
// abs err ~1e-7 for x >= ~0.5
__device__ __forceinline__ float lgf(float x) {
    float p = x * (x + 1.0f) * (x + 2.0f) * (x + 3.0f)
                * (x + 4.0f) * (x + 5.0f) * (x + 6.0f) * (x + 7.0f);
    float z  = x + 8.0f;
    float r  = __fdividef(1.0f, z);
    float lz = __logf(z);
    float lg = fmaf(z - 0.5f, lz, -z) + 0.91893853320467274f
             + r * fmaf(-0.0027777778f, r * r, 0.083333333f);
    return lg - __logf(p);
}

// ---- single fused kernel: block (b,k); 256 threads, one dim per thread ----
__global__ void __launch_bounds__(DD) k_main(const float* __restrict__ X,
                                             const int* __restrict__ z,
                                             const float* __restrict__ loc,
                                             const float* __restrict__ lcg,
                                             const float* __restrict__ lsc,
                                             const float* __restrict__ spl,
                                             float* __restrict__ out) {
    int bk = blockIdx.x;
    int b  = bk >> 6;                                 // / KK
    int k  = bk & (KK - 1);
    int tid = threadIdx.x;

    // ---- unordered bucket build (suffstats are order-independent) ----
    __shared__ int tbuf[TT];
    __shared__ int cnt_s;
    if (tid == 0) cnt_s = 0;
    __syncthreads();
    int4 zq = reinterpret_cast<const int4*>(z + b * TT)[tid];   // 4 t's per thread
    int t0 = tid * 4;
    if (zq.x == k) tbuf[atomicAdd(&cnt_s, 1)] = (t0 + 0) * DD;
    if (zq.y == k) tbuf[atomicAdd(&cnt_s, 1)] = (t0 + 1) * DD;
    if (zq.z == k) tbuf[atomicAdd(&cnt_s, 1)] = (t0 + 2) * DD;
    if (zq.w == k) tbuf[atomicAdd(&cnt_s, 1)] = (t0 + 3) * DD;
    __syncthreads();
    int cnt = cnt_s;

    // ---- gather + sufficient statistics (unroll 8 for MLP) ----
    const float* Xb = X + (size_t)b * TT * DD + tid;
    float n1 = 0.0f, S1 = 0.0f, S2 = 0.0f;

    int i = 0;
    for (; i + 8 <= cnt; i += 8) {
        float x0 = __ldg(Xb + tbuf[i + 0]);
        float x1 = __ldg(Xb + tbuf[i + 1]);
        float x2 = __ldg(Xb + tbuf[i + 2]);
        float x3 = __ldg(Xb + tbuf[i + 3]);
        float x4 = __ldg(Xb + tbuf[i + 4]);
        float x5 = __ldg(Xb + tbuf[i + 5]);
        float x6 = __ldg(Xb + tbuf[i + 6]);
        float x7 = __ldg(Xb + tbuf[i + 7]);
        float u0 = __logf(x0 > 0.0f ? x0 : 1.0f);
        float u1 = __logf(x1 > 0.0f ? x1 : 1.0f);
        float u2 = __logf(x2 > 0.0f ? x2 : 1.0f);
        float u3 = __logf(x3 > 0.0f ? x3 : 1.0f);
        float u4 = __logf(x4 > 0.0f ? x4 : 1.0f);
        float u5 = __logf(x5 > 0.0f ? x5 : 1.0f);
        float u6 = __logf(x6 > 0.0f ? x6 : 1.0f);
        float u7 = __logf(x7 > 0.0f ? x7 : 1.0f);
        S1 += ((u0 + u1) + (u2 + u3)) + ((u4 + u5) + (u6 + u7));
        S2 = fmaf(u0, u0, S2); S2 = fmaf(u1, u1, S2);
        S2 = fmaf(u2, u2, S2); S2 = fmaf(u3, u3, S2);
        S2 = fmaf(u4, u4, S2); S2 = fmaf(u5, u5, S2);
        S2 = fmaf(u6, u6, S2); S2 = fmaf(u7, u7, S2);
        n1 += ((x0 > 0.0f) + (x1 > 0.0f) + (x2 > 0.0f) + (x3 > 0.0f))
            + ((x4 > 0.0f) + (x5 > 0.0f) + (x6 > 0.0f) + (x7 > 0.0f));
    }
    for (; i < cnt; ++i) {
        float x = __ldg(Xb + tbuf[i]);
        float t = __logf(x > 0.0f ? x : 1.0f);
        S1 += t; S2 = fmaf(t, t, S2); n1 += (x > 0.0f);
    }

    // ---- epilogue from sufficient statistics (constants inline) ----
    float cc   = __expf(lcg[tid]);
    float m0   = loc[tid];
    float lb0  = lsc[tid];
    float b0   = __expf(lb0);
    float kap0 = 2.0f * cc + 3.0f;
    float tc4  = kap0 + 1.0f;
    float c00  = tc4 * __expf(spl[tid]);
    float cntf = (float)cnt;
    float n0f  = cntf - n1;

    // closed-form final NIG scale b_n (order independent)
    float rn   = (n1 > 0.0f) ? __fdividef(1.0f, n1) : 0.0f;
    float tbar = S1 * rn;
    float dm   = tbar - m0;
    float bb   = b0 + 0.5f * (S2 - S1 * tbar)
               + __fdividef(kap0 * n1 * dm * dm, 2.0f * (kap0 + n1));

    float acc = -S1;                                  // Jacobian
    acc -= 0.5f * n1 * lb0 + fmaf(0.5f, n1, cc) * (__logf(bb) - lb0);
    // static telescoped lgammas; 0.5lgf(tc4+n1)+0.5lgf(kap0+n1) = lgf(kap0+n1)+0.5log(kap0+n1)
    float kn = kap0 + n1;
    acc += lgf(fmaf(0.5f, n1, cc)) - lgf(cc)
         + lgf(kn) + 0.5f * __logf(kn) - lgf(kap0) - 0.5f * __logf(kap0)
         - 0.5f * n1 * LOG2PI;
    acc += lgf(c00 + n0f) - lgf(c00)
         + lgf(tc4 + c00) - lgf(tc4 + c00 + cntf);

    // CRP numerator for this (b,k): lgamma(cnt)   (ALPHA=1) — fold into thread 0
    if (tid == 0 && cnt > 0) acc += lgf(cntf);

    // ---- block reduce (256 threads) ----
#pragma unroll
    for (int o = 16; o; o >>= 1) acc += __shfl_xor_sync(0xffffffffu, acc, o);
    __shared__ float wsum[DD / 32];
    int lane = tid & 31, wid = tid >> 5;
    if (lane == 0) wsum[wid] = acc;
    __syncthreads();
    if (tid == 0) {
        float s = 0.0f;
#pragma unroll
        for (int w = 0; w < DD / 32; ++w) s += wsum[w];
        atomicAdd(&g_acc, (double)s);
        __threadfence();
        int prev = atomicAdd(&g_done, 1);
        if (prev == NBLK - 1) {
            double tot = atomicAdd(&g_acc, 0.0);      // read-after-fence
            // CRP denominator: per-batch lgamma(T+1)
            tot -= (double)BB * (double)lgf((float)(TT + 1));
            out[0] = (float)(-tot / (double)BB);
            g_acc  = 0.0;                             // restore for next replay
            g_done = 0;
        }
    }
}

extern "C" void kernel_launch(void* const* d_in, const int* in_sizes, int n_in,
                              void* d_out, int out_size) {
    const float* X   = (const float*)d_in[0];
    const int*   z   = (const int*)d_in[1];
    const float* loc = (const float*)d_in[2];
    const float* lcg = (const float*)d_in[3];
    const float* lsc = (const float*)d_in[4];
    const float* spl = (const float*)d_in[5];

    k_main<<<NBLK, DD>>>(X, z, loc, lcg, lsc, spl, (float*)d_out);
}